// round 13
// baseline (speedup 1.0000x reference)
#include <cuda_runtime.h>

#define NQ 12
#define DIMS 4096
#define GROUPS 6
#define THREADS (64 * GROUPS)   // 384

using u64 = unsigned long long;

// ---- packed f32x2 helpers ----
__device__ __forceinline__ u64 pk2(float lo, float hi) {
    u64 r; asm("mov.b64 %0,{%1,%2};" : "=l"(r) : "f"(lo), "f"(hi)); return r;
}
__device__ __forceinline__ void upk2(u64 v, float& lo, float& hi) {
    asm("mov.b64 {%0,%1},%2;" : "=f"(lo), "=f"(hi) : "l"(v));
}
__device__ __forceinline__ u64 fma2(u64 a, u64 b, u64 c) {
    u64 d; asm("fma.rn.f32x2 %0,%1,%2,%3;" : "=l"(d) : "l"(a), "l"(b), "l"(c)); return d;
}
__device__ __forceinline__ u64 mul2(u64 a, u64 b) {
    u64 d; asm("mul.rn.f32x2 %0,%1,%2;" : "=l"(d) : "l"(a), "l"(b)); return d;
}

// Ring-CNOT permutation: new_state[i] = old_state[perm_fwd(i)]
__device__ __forceinline__ int perm_fwd(int i) {
#pragma unroll
    for (int j = 11; j >= 0; j--) {
        int cb = 11 - j;
        int tb = (j == 11) ? 11 : (10 - j);
        i ^= ((i >> cb) & 1) << tb;
    }
    return i;
}
__device__ __forceinline__ int perm_inv(int i) {
#pragma unroll
    for (int j = 0; j < 12; j++) {
        int cb = 11 - j;
        int tb = (j == 11) ? 11 : (10 - j);
        i ^= ((i >> cb) & 1) << tb;
    }
    return i;
}

// Layout A (pass1 stores -> pass2 float4 loads): physA(i)=i^(((i>>6)&7)<<1)
// Layout B (pass2 stores -> pass1 perm-loads):  physB(j)=j^(((j>>6)&7)<<1)^((j>>9)&1)
__device__ __forceinline__ int layB(int j) {
    return j ^ (((j >> 6) & 7) << 1) ^ ((j >> 9) & 1);
}

__global__ void __launch_bounds__(THREADS, 1) qsim_kernel(
    const float* __restrict__ x, const float* __restrict__ w,
    float* __restrict__ out, int Btot)
{
    extern __shared__ unsigned char dsm[];
    float2* stA = (float2*)dsm;                                // 6*4096 float2
    float*  fp  = (float*)(dsm + GROUPS * DIMS * sizeof(float2));
    float* gcA = fp;                     // GROUPS*48
    float* gsA = gcA + GROUPS * 48;
    float* gtA = gsA + GROUPS * 48;
    float* luA = gtA + GROUPS * 48;      // GROUPS*48 (LUT: 16+16+16)
    float* reA = luA + GROUPS * 48;      // GROUPS*12
    float* s2A = reA + GROUPS * NQ;      // GROUPS

    const int tid = threadIdx.x;
    const int h = tid >> 6;              // sample group 0..5
    const int t = tid & 63;              // worker thread within group
    const int b = blockIdx.x * GROUPS + h;
    if (b >= Btot) return;               // inactive group: its barrier never used

    float2* st = stA + h * DIMS;
    float* gc = gcA + h * 48;
    float* gs = gsA + h * 48;
    float* gt = gtA + h * 48;
    float* sLA = luA + h * 48;
    float* sLB = sLA + 16;
    float* sLC = sLA + 32;
    float* red = reA + h * NQ;

    const int pt = perm_fwd(t);

    // Per-group barrier (2 warps, id = h+1)
    auto NB = [&]() { asm volatile("bar.sync %0, %1;" :: "r"(h + 1), "r"(64) : "memory"); };

    // Angles: slots 0-11 = x_q + w_{0,q} (RX fusion); 12-47 = w rows 1-3.
    if (t < 48) {
        float th = w[t];
        if (t < NQ) th += x[b * NQ + t];
        float ss, cc;
        sincosf(0.5f * th, &ss, &cc);
        gc[t] = cc; gs[t] = ss;
        gt[t] = ss / cc;
    }
    if (t < NQ) red[t] = 0.0f;
    NB();

    // Product-state magnitude LUTs over the three 4-bit nibbles (exact c,s).
    if (t < 48) {
        int grp = t >> 4;
        int hh = t & 15;
        int qbase = grp * 4;
        float p = 1.0f;
#pragma unroll
        for (int q = 0; q < 4; q++)
            p *= ((hh >> (3 - q)) & 1) ? gs[qbase + q] : gc[qbase + q];
        sLA[grp * 16 + hh] = p;          // contiguous LUT block
    }
    if (t == 0) {
        float S = 1.0f;
#pragma unroll
        for (int g = 12; g < 48; g++) S *= gc[g];
        s2A[h] = S * S;
    }

    // SoA packed state: slot k holds LOGICAL amps l=2k, 2k+1 (l = 6 bits).
    u64 X[32], Y[32];

    auto gate_pack = [&](float2 a0, float2 a1, float t1, int k) {
        float nx0 = fmaf( t1, a1.y, a0.x);
        float ny0 = fmaf(-t1, a1.x, a0.y);
        float nx1 = fmaf( t1, a0.y, a1.x);
        float ny1 = fmaf(-t1, a0.x, a1.y);
        X[k] = pk2(nx0, nx1);
        Y[k] = pk2(ny0, ny1);
    };

    auto rxp = [&](int g, int pm) {
        float tg = gt[g];
        u64 t2 = pk2(tg, tg), m2 = pk2(-tg, -tg);
#pragma unroll
        for (int k = 0; k < 32; k++) {
            if (!(k & pm)) {
                int k1 = k | pm;
                u64 X0 = X[k], Y0 = Y[k], X1 = X[k1], Y1 = Y[k1];
                X[k]  = fma2(t2, Y1, X0);
                Y[k]  = fma2(m2, X1, Y0);
                X[k1] = fma2(t2, Y0, X1);
                Y[k1] = fma2(m2, X0, Y1);
            }
        }
    };
    auto packed5_p1 = [&](int g) {
        rxp(g, 16); rxp(g + 1, 8); rxp(g + 2, 4); rxp(g + 3, 2); rxp(g + 4, 1);
    };
    auto packed5_p2 = [&](int g) {
        rxp(g + 6, 16); rxp(g + 7, 8); rxp(g + 8, 4); rxp(g + 9, 2); rxp(g + 10, 1);
    };

    auto prod_amp = [&](int pi) -> float2 {
        float mag = sLA[pi >> 8] * sLB[(pi >> 4) & 15] * sLC[pi & 15];
        int kc = __popc(pi) & 3;
        float sm = __int_as_float(__float_as_int(mag) ^ (((kc + 1) & 2) << 30));
        return (kc & 1) ? make_float2(0.0f, sm) : make_float2(sm, 0.0f);
    };

    // pass1 perm-load (layers 2,3): i=(l<<6)|t from Layout B at layB(perm_fwd(i));
    // load-time gate = qubit 5 (g+5) on l-bit 0.
    auto p1_load_perm = [&](int g) {
        float t1 = gt[g + 5];
#pragma unroll
        for (int k = 0; k < 32; k++) {
            int A0 = perm_fwd((2 * k) << 6) ^ pt;
            int A1 = perm_fwd((2 * k + 1) << 6) ^ pt;
            gate_pack(st[layB(A0)], st[layB(A1)], t1, k);
        }
    };
    // pass1 store into Layout A
    auto p1_store = [&]() {
#pragma unroll
        for (int k = 0; k < 32; k++) {
            float x0, x1, y0, y1;
            upk2(X[k], x0, x1);
            upk2(Y[k], y0, y1);
            int l0 = 2 * k, l1 = 2 * k + 1;
            st[((l0 << 6) | t) ^ ((l0 & 7) << 1)] = make_float2(x0, y0);
            st[((l1 << 6) | t) ^ ((l1 & 7) << 1)] = make_float2(x1, y1);
        }
    };
    // pass2 float4 load from Layout A; load-time gate = qubit 11 (g+11).
    auto p2_load = [&](int g) {
        float t1 = gt[g + 11];
        const float4* st4 = reinterpret_cast<const float4*>(st);
        int base = t << 5, key = t & 7;
#pragma unroll
        for (int k = 0; k < 32; k++) {
            float4 v = st4[base | (k ^ key)];
            gate_pack(make_float2(v.x, v.y), make_float2(v.z, v.w), t1, k);
        }
    };
    // pass2 store into Layout B (thread-private 64-entry block)
    auto p2_store = [&]() {
        int base = (t << 6);
        int key = ((t & 7) << 1) | ((t >> 3) & 1);
#pragma unroll
        for (int k = 0; k < 32; k++) {
            float x0, x1, y0, y1;
            upk2(X[k], x0, x1);
            upk2(Y[k], y0, y1);
            st[base | ((2 * k) ^ key)]     = make_float2(x0, y0);
            st[base | ((2 * k + 1) ^ key)] = make_float2(x1, y1);
        }
    };

    NB();  // LUTs + sS2 ready

    // ---- Layer 1 (gates 12-23): pass1 analytic at perm-permuted indices ----
    {
        float t1 = gt[12 + 5];
#pragma unroll
        for (int k = 0; k < 32; k++)
            gate_pack(prod_amp(perm_fwd((2 * k) << 6) ^ pt),
                      prod_amp(perm_fwd((2 * k + 1) << 6) ^ pt), t1, k);
        packed5_p1(12);
        p1_store(); NB();
        p2_load(12); packed5_p2(12); p2_store(); NB();
    }

    // ---- Layers 2,3 (gates 24-35, 36-47) ----
#pragma unroll 1
    for (int layer = 2; layer <= 3; layer++) {
        int g = layer * 12;
        p1_load_perm(g);
        packed5_p1(g);
        NB();                      // scattered reads done before overwrite
        p1_store(); NB();
        p2_load(g); packed5_p2(g);
        if (layer < 3) { p2_store(); NB(); }
        // layer 3: stays in registers; final perm folded into readout
    }

    // ---- Readout: <Z_q> = S^2 * sum_i p_i * (1-2*bit_{11-q}(perm_inv(i))) ----
    u64 acc2[NQ];
    const u64 spp = pk2( 1.0f,  1.0f), spm = pk2( 1.0f, -1.0f);
    const u64 smp = pk2(-1.0f,  1.0f), smm = pk2(-1.0f, -1.0f);
#pragma unroll
    for (int q = 0; q < NQ; q++) acc2[q] = 0ull;
#pragma unroll
    for (int k = 0; k < 32; k++) {
        u64 P = fma2(X[k], X[k], mul2(Y[k], Y[k]));
        const int pil0 = perm_inv(2 * k);      // compile-time constants
        const int pil1 = perm_inv(2 * k + 1);
#pragma unroll
        for (int q = 0; q < NQ; q++) {
            bool n0 = (pil0 >> (11 - q)) & 1;
            bool n1 = (pil1 >> (11 - q)) & 1;
            u64 sgn = n0 ? (n1 ? smm : smp) : (n1 ? spm : spp);
            acc2[q] = fma2(sgn, P, acc2[q]);
        }
    }
    float acc[NQ];
    {
        int pit = perm_inv(t << 6);
#pragma unroll
        for (int q = 0; q < NQ; q++) {
            float a0, a1;
            upk2(acc2[q], a0, a1);
            float s = a0 + a1;
            acc[q] = __int_as_float(__float_as_int(s) ^
                                    (((pit >> (11 - q)) & 1) << 31));
        }
    }
#pragma unroll
    for (int off = 16; off > 0; off >>= 1) {
#pragma unroll
        for (int q = 0; q < NQ; q++)
            acc[q] += __shfl_xor_sync(0xffffffffu, acc[q], off);
    }
    if ((t & 31) == 0) {
#pragma unroll
        for (int q = 0; q < NQ; q++) atomicAdd(&red[q], acc[q]);
    }
    NB();
    if (t < NQ) out[b * NQ + t] = red[t] * s2A[h];
}

extern "C" void kernel_launch(void* const* d_in, const int* in_sizes, int n_in,
                              void* d_out, int out_size) {
    const float* x = (const float*)d_in[0];   // (64,128,12) float32
    const float* w = (const float*)d_in[1];   // (4,12) float32
    float* out = (float*)d_out;               // (64,128,12) float32
    int B = in_sizes[0] / NQ;                 // 8192

    // 6 * (32KB state + 4*48 floats + 12 + 1) = ~201.6 KB dynamic smem
    const int smem_bytes =
        GROUPS * (DIMS * (int)sizeof(float2) + (48 * 4 + NQ + 1) * (int)sizeof(float));
    static bool attr_done = false;
    // Attribute set is idempotent; do it on every call (no static-guard work skip —
    // the launch below always happens).
    cudaFuncSetAttribute(qsim_kernel, cudaFuncAttributeMaxDynamicSharedMemorySize,
                         smem_bytes);
    (void)attr_done;
    int grid = (B + GROUPS - 1) / GROUPS;     // 1366
    qsim_kernel<<<grid, THREADS, smem_bytes>>>(x, w, out, B);
}

// round 14
// speedup vs baseline: 1.0233x; 1.0233x over previous
#include <cuda_runtime.h>

#define THREADS 64
#define NQ 12
#define DIM 4096

using u64 = unsigned long long;

// ---- packed f32x2 helpers ----
__device__ __forceinline__ u64 pk2(float lo, float hi) {
    u64 r; asm("mov.b64 %0,{%1,%2};" : "=l"(r) : "f"(lo), "f"(hi)); return r;
}
__device__ __forceinline__ void upk2(u64 v, float& lo, float& hi) {
    asm("mov.b64 {%0,%1},%2;" : "=f"(lo), "=f"(hi) : "l"(v));
}
__device__ __forceinline__ u64 fma2(u64 a, u64 b, u64 c) {
    u64 d; asm("fma.rn.f32x2 %0,%1,%2,%3;" : "=l"(d) : "l"(a), "l"(b), "l"(c)); return d;
}
__device__ __forceinline__ u64 mul2(u64 a, u64 b) {
    u64 d; asm("mul.rn.f32x2 %0,%1,%2;" : "=l"(d) : "l"(a), "l"(b)); return d;
}

// Ring-CNOT permutation: new_state[i] = old_state[perm_fwd(i)]
__device__ __forceinline__ int perm_fwd(int i) {
#pragma unroll
    for (int j = 11; j >= 0; j--) {
        int cb = 11 - j;
        int tb = (j == 11) ? 11 : (10 - j);
        i ^= ((i >> cb) & 1) << tb;
    }
    return i;
}
__device__ __forceinline__ int perm_inv(int i) {
#pragma unroll
    for (int j = 0; j < 12; j++) {
        int cb = 11 - j;
        int tb = (j == 11) ? 11 : (10 - j);
        i ^= ((i >> cb) & 1) << tb;
    }
    return i;
}

// Layout A (pass1 stores -> pass2 float4 loads): physA(i)=i^(((i>>6)&7)<<1)
// Layout B (pass2 stores -> pass1 perm-loads):  physB(j)=j^(((j>>6)&7)<<1)^((j>>9)&1)
// Both are GF(2)-linear -> layB(C ^ pt) = layB(C) ^ layB(pt); the C part
// constant-folds, the pt part is hoisted out of the access loops.
__device__ __forceinline__ int layB(int j) {
    return j ^ (((j >> 6) & 7) << 1) ^ ((j >> 9) & 1);
}

__global__ void __launch_bounds__(THREADS, 6) qsim_kernel(
    const float* __restrict__ x, const float* __restrict__ w,
    float* __restrict__ out)
{
    __shared__ float2 st[DIM];          // 32 KB state
    __shared__ float gc[48], gs[48];    // cos/sin (0-11 = merged encode+layer0)
    __shared__ float gt[48];            // tan(theta/2) (slots 12-47 consumed)
    __shared__ float sLA[16], sLB[16], sLC[16];  // product-state magnitude LUTs
    __shared__ float red[NQ];
    __shared__ float sS2;               // (prod c over gates 12..47)^2

    const int b = blockIdx.x;
    const int t = threadIdx.x;          // 0..63
    const int pt = perm_fwd(t);
    const int ptB = layB(pt);           // hoisted: per-access addr = CONST ^ ptB

    // Angles: slots 0-11 = x_q + w_{0,q} (RX fusion); 12-47 = w rows 1-3.
    if (t < 48) {
        float th = w[t];
        if (t < NQ) th += x[b * NQ + t];
        float ss, cc;
        sincosf(0.5f * th, &ss, &cc);
        gc[t] = cc; gs[t] = ss;
        gt[t] = ss / cc;
    }
    if (t < NQ) red[t] = 0.0f;
    __syncthreads();

    // Product-state magnitude LUTs over the three 4-bit nibbles (exact c,s).
    if (t < 48) {
        int grp = t >> 4;
        int h = t & 15;
        int qbase = grp * 4;
        float p = 1.0f;
#pragma unroll
        for (int q = 0; q < 4; q++)
            p *= ((h >> (3 - q)) & 1) ? gs[qbase + q] : gc[qbase + q];
        (grp == 0 ? sLA : grp == 1 ? sLB : sLC)[h] = p;
    }
    if (t == 0) {
        float S = 1.0f;
#pragma unroll
        for (int g = 12; g < 48; g++) S *= gc[g];
        sS2 = S * S;
    }

    // SoA packed state: slot k holds LOGICAL amps l=2k, 2k+1 (l = 6 bits).
    u64 X[32], Y[32];

    // pair-bit gate in tangent form on a freshly loaded pair, then pack.
    auto gate_pack = [&](float2 a0, float2 a1, float t1, int k) {
        float nx0 = fmaf( t1, a1.y, a0.x);
        float ny0 = fmaf(-t1, a1.x, a0.y);
        float nx1 = fmaf( t1, a0.y, a1.x);
        float ny1 = fmaf(-t1, a0.x, a1.y);
        X[k] = pk2(nx0, nx1);
        Y[k] = pk2(ny0, ny1);
    };

    // Packed tangent-form RX on pack-space bit pm (k in [0,32)).
    auto rxp = [&](int g, int pm) {
        float tg = gt[g];
        u64 t2 = pk2(tg, tg), m2 = pk2(-tg, -tg);
#pragma unroll
        for (int k = 0; k < 32; k++) {
            if (!(k & pm)) {
                int k1 = k | pm;
                u64 X0 = X[k], Y0 = Y[k], X1 = X[k1], Y1 = Y[k1];
                X[k]  = fma2(t2, Y1, X0);
                Y[k]  = fma2(m2, X1, Y0);
                X[k1] = fma2(t2, Y0, X1);
                Y[k1] = fma2(m2, X0, Y1);
            }
        }
    };
    // pass1: amps i=(l<<6)|t, register bits = qubits 0..5. Packed: qubits 0..4.
    auto packed5_p1 = [&](int g) {
        rxp(g, 16); rxp(g + 1, 8); rxp(g + 2, 4); rxp(g + 3, 2); rxp(g + 4, 1);
    };
    // pass2: amps i=(t<<6)|l, register bits = qubits 6..11. Packed: qubits 6..10.
    auto packed5_p2 = [&](int g) {
        rxp(g + 6, 16); rxp(g + 7, 8); rxp(g + 8, 4); rxp(g + 9, 2); rxp(g + 10, 1);
    };

    // Analytic product-state amplitude: amp = mag(pi) * (-i)^popc(pi)
    auto prod_amp = [&](int pi) -> float2 {
        float mag = sLA[pi >> 8] * sLB[(pi >> 4) & 15] * sLC[pi & 15];
        int kc = __popc(pi) & 3;
        float sm = __int_as_float(__float_as_int(mag) ^ (((kc + 1) & 2) << 30));
        return (kc & 1) ? make_float2(0.0f, sm) : make_float2(sm, 0.0f);
    };

    // pass1 perm-load (layers 2,3): amps i=(l<<6)|t from Layout B.
    // Address = layB(perm_fwd(l<<6) ^ pt) = layB(perm_fwd(l<<6)) ^ ptB:
    // the first term constant-folds -> ONE LOP3 per access.
    auto p1_load_perm = [&](int g) {
        float t1 = gt[g + 5];
#pragma unroll
        for (int k = 0; k < 32; k++) {
            const int LB0 = layB(perm_fwd((2 * k) << 6));      // compile-time
            const int LB1 = layB(perm_fwd((2 * k + 1) << 6));  // compile-time
            gate_pack(st[LB0 ^ ptB], st[LB1 ^ ptB], t1, k);
        }
    };
    // pass1 store into Layout A: addr = CONST_l ^ t (single LOP3 per store).
    auto p1_store = [&]() {
#pragma unroll
        for (int k = 0; k < 32; k++) {
            float x0, x1, y0, y1;
            upk2(X[k], x0, x1);
            upk2(Y[k], y0, y1);
            const int l0 = 2 * k, l1 = 2 * k + 1;
            const int C0 = (l0 << 6) ^ ((l0 & 7) << 1);        // compile-time
            const int C1 = (l1 << 6) ^ ((l1 & 7) << 1);        // compile-time
            st[C0 ^ t] = make_float2(x0, y0);
            st[C1 ^ t] = make_float2(x1, y1);
        }
    };
    // pass2 float4 load from Layout A: phys4 = (t<<5)|(k^(t&7)) holds logical
    // pack k (amps (t<<6)|2k, +1). Load-time gate = qubit 11 (g+11).
    auto p2_load = [&](int g) {
        float t1 = gt[g + 11];
        const float4* st4 = reinterpret_cast<const float4*>(st);
        int base = t << 5, key = t & 7;
#pragma unroll
        for (int k = 0; k < 32; k++) {
            float4 v = st4[base | (k ^ key)];
            gate_pack(make_float2(v.x, v.y), make_float2(v.z, v.w), t1, k);
        }
    };
    // pass2 store into Layout B: phys = (t<<6) | (l ^ (((t&7)<<1)|((t>>3)&1)))
    // (thread-private 64-entry block; no intra-pass sync needed)
    auto p2_store = [&]() {
        int base = (t << 6);
        int key = ((t & 7) << 1) | ((t >> 3) & 1);
#pragma unroll
        for (int k = 0; k < 32; k++) {
            float x0, x1, y0, y1;
            upk2(X[k], x0, x1);
            upk2(Y[k], y0, y1);
            st[base | ((2 * k) ^ key)]     = make_float2(x0, y0);
            st[base | ((2 * k + 1) ^ key)] = make_float2(x1, y1);
        }
    };

    __syncthreads();  // LUTs + sS2 ready

    // ---- Layer 1 (gates 12-23) ----
    // pass1: analytic amps at perm-permuted indices of the merged product state
    {
        float t1 = gt[12 + 5];
#pragma unroll
        for (int k = 0; k < 32; k++)
            gate_pack(prod_amp(perm_fwd((2 * k) << 6) ^ pt),
                      prod_amp(perm_fwd((2 * k + 1) << 6) ^ pt), t1, k);
        packed5_p1(12);
        p1_store(); __syncthreads();
        p2_load(12); packed5_p2(12); p2_store(); __syncthreads();
    }

    // ---- Layers 2,3 (gates 24-35, 36-47) ----
#pragma unroll 1
    for (int layer = 2; layer <= 3; layer++) {
        int g = layer * 12;
        p1_load_perm(g);
        packed5_p1(g);
        __syncthreads();               // scattered reads done before overwrite
        p1_store(); __syncthreads();
        p2_load(g); packed5_p2(g);
        if (layer < 3) { p2_store(); __syncthreads(); }
        // layer 3: stays in registers; final perm folded into readout
    }

    // ---- Readout: <Z_q> = S^2 * sum_i p_i * (1-2*bit_{11-q}(perm_inv(i))) ----
    u64 acc2[NQ];
    const u64 spp = pk2( 1.0f,  1.0f), spm = pk2( 1.0f, -1.0f);
    const u64 smp = pk2(-1.0f,  1.0f), smm = pk2(-1.0f, -1.0f);
#pragma unroll
    for (int q = 0; q < NQ; q++) acc2[q] = 0ull;
#pragma unroll
    for (int k = 0; k < 32; k++) {
        u64 P = fma2(X[k], X[k], mul2(Y[k], Y[k]));
        const int pil0 = perm_inv(2 * k);      // compile-time constants
        const int pil1 = perm_inv(2 * k + 1);
#pragma unroll
        for (int q = 0; q < NQ; q++) {
            bool n0 = (pil0 >> (11 - q)) & 1;
            bool n1 = (pil1 >> (11 - q)) & 1;
            u64 sgn = n0 ? (n1 ? smm : smp) : (n1 ? spm : spp);
            acc2[q] = fma2(sgn, P, acc2[q]);
        }
    }
    float acc[NQ];
    {
        int pit = perm_inv(t << 6);   // runtime per-thread sign factor
#pragma unroll
        for (int q = 0; q < NQ; q++) {
            float a0, a1;
            upk2(acc2[q], a0, a1);
            float s = a0 + a1;
            acc[q] = __int_as_float(__float_as_int(s) ^
                                    (((pit >> (11 - q)) & 1) << 31));
        }
    }
#pragma unroll
    for (int off = 16; off > 0; off >>= 1) {
#pragma unroll
        for (int q = 0; q < NQ; q++)
            acc[q] += __shfl_xor_sync(0xffffffffu, acc[q], off);
    }
    if ((t & 31) == 0) {
#pragma unroll
        for (int q = 0; q < NQ; q++) atomicAdd(&red[q], acc[q]);
    }
    __syncthreads();
    if (t < NQ) out[b * NQ + t] = red[t] * sS2;  // apply deferred scale once
}

extern "C" void kernel_launch(void* const* d_in, const int* in_sizes, int n_in,
                              void* d_out, int out_size) {
    const float* x = (const float*)d_in[0];   // (64,128,12) float32
    const float* w = (const float*)d_in[1];   // (4,12) float32
    float* out = (float*)d_out;               // (64,128,12) float32
    int B = in_sizes[0] / NQ;                 // 8192
    qsim_kernel<<<B, THREADS>>>(x, w, out);
}

// round 15
// speedup vs baseline: 1.1459x; 1.1198x over previous
#include <cuda_runtime.h>

#define THREADS 64
#define NQ 12
#define DIM 4096

using u64 = unsigned long long;

// ---- packed f32x2 helpers ----
__device__ __forceinline__ u64 pk2(float lo, float hi) {
    u64 r; asm("mov.b64 %0,{%1,%2};" : "=l"(r) : "f"(lo), "f"(hi)); return r;
}
__device__ __forceinline__ void upk2(u64 v, float& lo, float& hi) {
    asm("mov.b64 {%0,%1},%2;" : "=f"(lo), "=f"(hi) : "l"(v));
}
__device__ __forceinline__ u64 fma2(u64 a, u64 b, u64 c) {
    u64 d; asm("fma.rn.f32x2 %0,%1,%2,%3;" : "=l"(d) : "l"(a), "l"(b), "l"(c)); return d;
}
__device__ __forceinline__ u64 mul2(u64 a, u64 b) {
    u64 d; asm("mul.rn.f32x2 %0,%1,%2;" : "=l"(d) : "l"(a), "l"(b)); return d;
}

// Ring-CNOT permutation: new_state[i] = old_state[perm_fwd(i)]
__device__ __forceinline__ int perm_fwd(int i) {
#pragma unroll
    for (int j = 11; j >= 0; j--) {
        int cb = 11 - j;
        int tb = (j == 11) ? 11 : (10 - j);
        i ^= ((i >> cb) & 1) << tb;
    }
    return i;
}
__device__ __forceinline__ int perm_inv(int i) {
#pragma unroll
    for (int j = 0; j < 12; j++) {
        int cb = 11 - j;
        int tb = (j == 11) ? 11 : (10 - j);
        i ^= ((i >> cb) & 1) << tb;
    }
    return i;
}

// Layout A (pass1 stores -> pass2 float4 loads): physA(i)=i^(((i>>6)&7)<<1)
// Layout B (pass2 stores -> pass1 perm-loads):  physB(j)=j^(((j>>6)&7)<<1)^((j>>9)&1)
__device__ __forceinline__ int layB(int j) {
    return j ^ (((j >> 6) & 7) << 1) ^ ((j >> 9) & 1);
}

__global__ void __launch_bounds__(THREADS, 6) qsim_kernel(
    const float* __restrict__ x, const float* __restrict__ w,
    float* __restrict__ out)
{
    __shared__ float2 st[DIM];          // 32 KB state
    __shared__ float gc[48], gs[48];    // cos/sin (0-11 = merged encode+layer0)
    __shared__ float gt[48];            // tan(theta/2) (slots 12-47 consumed)
    __shared__ float sLA[16], sLB[16], sLC[16];  // product-state magnitude LUTs
    __shared__ float red[NQ];
    __shared__ float sS2;               // (prod c over gates 12..47)^2

    const int b = blockIdx.x;
    const int t = threadIdx.x;          // 0..63
    const int pt = perm_fwd(t);

    // Angles: slots 0-11 = x_q + w_{0,q} (RX fusion); 12-47 = w rows 1-3.
    if (t < 48) {
        float th = w[t];
        if (t < NQ) th += x[b * NQ + t];
        float ss, cc;
        sincosf(0.5f * th, &ss, &cc);
        gc[t] = cc; gs[t] = ss;
        gt[t] = ss / cc;
    }
    if (t < NQ) red[t] = 0.0f;
    __syncthreads();

    // Product-state magnitude LUTs over the three 4-bit nibbles (exact c,s).
    if (t < 48) {
        int grp = t >> 4;
        int h = t & 15;
        int qbase = grp * 4;
        float p = 1.0f;
#pragma unroll
        for (int q = 0; q < 4; q++)
            p *= ((h >> (3 - q)) & 1) ? gs[qbase + q] : gc[qbase + q];
        (grp == 0 ? sLA : grp == 1 ? sLB : sLC)[h] = p;
    }
    if (t == 0) {
        float S = 1.0f;
#pragma unroll
        for (int g = 12; g < 48; g++) S *= gc[g];
        sS2 = S * S;
    }

    // SoA packed state: slot k holds LOGICAL amps l=2k, 2k+1 (l = 6 bits).
    u64 X[32], Y[32];

    // pair-bit gate in tangent form on a freshly loaded pair, then pack.
    auto gate_pack = [&](float2 a0, float2 a1, float t1, int k) {
        float nx0 = fmaf( t1, a1.y, a0.x);
        float ny0 = fmaf(-t1, a1.x, a0.y);
        float nx1 = fmaf( t1, a0.y, a1.x);
        float ny1 = fmaf(-t1, a0.x, a1.y);
        X[k] = pk2(nx0, nx1);
        Y[k] = pk2(ny0, ny1);
    };

    // Packed tangent-form RX on pack-space bit pm (k in [0,32)).
    auto rxp = [&](int g, int pm) {
        float tg = gt[g];
        u64 t2 = pk2(tg, tg), m2 = pk2(-tg, -tg);
#pragma unroll
        for (int k = 0; k < 32; k++) {
            if (!(k & pm)) {
                int k1 = k | pm;
                u64 X0 = X[k], Y0 = Y[k], X1 = X[k1], Y1 = Y[k1];
                X[k]  = fma2(t2, Y1, X0);
                Y[k]  = fma2(m2, X1, Y0);
                X[k1] = fma2(t2, Y0, X1);
                Y[k1] = fma2(m2, X0, Y1);
            }
        }
    };
    // pass1: amps i=(l<<6)|t, register bits = qubits 0..5. Packed: qubits 0..4.
    auto packed5_p1 = [&](int g) {
        rxp(g, 16); rxp(g + 1, 8); rxp(g + 2, 4); rxp(g + 3, 2); rxp(g + 4, 1);
    };
    // pass2: amps i=(t<<6)|l, register bits = qubits 6..11. Packed: qubits 6..10.
    auto packed5_p2 = [&](int g) {
        rxp(g + 6, 16); rxp(g + 7, 8); rxp(g + 8, 4); rxp(g + 9, 2); rxp(g + 10, 1);
    };

    // Analytic product-state amplitude: amp = mag(pi) * (-i)^popc(pi)
    auto prod_amp = [&](int pi) -> float2 {
        float mag = sLA[pi >> 8] * sLB[(pi >> 4) & 15] * sLC[pi & 15];
        int kc = __popc(pi) & 3;
        float sm = __int_as_float(__float_as_int(mag) ^ (((kc + 1) & 2) << 30));
        return (kc & 1) ? make_float2(0.0f, sm) : make_float2(sm, 0.0f);
    };

    // pass1 perm-load (layers 2,3): amps i=(l<<6)|t from Layout B at
    // layB(perm_fwd(i)); load-time gate = qubit 5 (g+5) on l-bit 0.
    auto p1_load_perm = [&](int g) {
        float t1 = gt[g + 5];
#pragma unroll
        for (int k = 0; k < 32; k++) {
            int A0 = perm_fwd((2 * k) << 6) ^ pt;
            int A1 = perm_fwd((2 * k + 1) << 6) ^ pt;
            gate_pack(st[layB(A0)], st[layB(A1)], t1, k);
        }
    };
    // pass1 store into Layout A
    auto p1_store = [&]() {
#pragma unroll
        for (int k = 0; k < 32; k++) {
            float x0, x1, y0, y1;
            upk2(X[k], x0, x1);
            upk2(Y[k], y0, y1);
            int l0 = 2 * k, l1 = 2 * k + 1;
            st[((l0 << 6) | t) ^ ((l0 & 7) << 1)] = make_float2(x0, y0);
            st[((l1 << 6) | t) ^ ((l1 & 7) << 1)] = make_float2(x1, y1);
        }
    };
    // pass2 float4 load from Layout A; load-time gate = qubit 11 (g+11).
    auto p2_load = [&](int g) {
        float t1 = gt[g + 11];
        const float4* st4 = reinterpret_cast<const float4*>(st);
        int base = t << 5, key = t & 7;
#pragma unroll
        for (int k = 0; k < 32; k++) {
            float4 v = st4[base | (k ^ key)];
            gate_pack(make_float2(v.x, v.y), make_float2(v.z, v.w), t1, k);
        }
    };
    // pass2 store into Layout B (thread-private 64-entry block)
    auto p2_store = [&]() {
        int base = (t << 6);
        int key = ((t & 7) << 1) | ((t >> 3) & 1);
#pragma unroll
        for (int k = 0; k < 32; k++) {
            float x0, x1, y0, y1;
            upk2(X[k], x0, x1);
            upk2(Y[k], y0, y1);
            st[base | ((2 * k) ^ key)]     = make_float2(x0, y0);
            st[base | ((2 * k + 1) ^ key)] = make_float2(x1, y1);
        }
    };

    __syncthreads();  // LUTs + sS2 ready

    // ---- Layer 1 (gates 12-23): pass1 analytic at perm-permuted indices ----
    {
        float t1 = gt[12 + 5];
#pragma unroll
        for (int k = 0; k < 32; k++)
            gate_pack(prod_amp(perm_fwd((2 * k) << 6) ^ pt),
                      prod_amp(perm_fwd((2 * k + 1) << 6) ^ pt), t1, k);
        packed5_p1(12);
        p1_store(); __syncthreads();
        p2_load(12); packed5_p2(12); p2_store(); __syncthreads();
    }

    // ---- Layers 2,3 (gates 24-35, 36-47) ----
#pragma unroll 1
    for (int layer = 2; layer <= 3; layer++) {
        int g = layer * 12;
        p1_load_perm(g);
        packed5_p1(g);
        __syncthreads();               // scattered reads done before overwrite
        p1_store(); __syncthreads();
        p2_load(g); packed5_p2(g);
        if (layer < 3) { p2_store(); __syncthreads(); }
        // layer 3: stays in registers; final perm folded into readout
    }

    // ---- Readout via Walsh-Hadamard transform ----
    // <Z_q> = S^2 * sum_i p_i * (-1)^{bit_{11-q}(perm_inv(i))}
    //       = S^2 * (-1)^{<row_q, t-part>} * What_p[mu_q]
    // where mu_q = perm_inv-row restricted to the 6 l-bits. Compute the full
    // 64-pt WHT over l with 5 packed butterfly levels + within-pack select.
    u64 P[32];
#pragma unroll
    for (int k = 0; k < 32; k++)
        P[k] = fma2(X[k], X[k], mul2(Y[k], Y[k]));   // packed |amp|^2 pairs

    const u64 pOne = pk2(1.0f, 1.0f), mOne = pk2(-1.0f, -1.0f);
    auto wht_level = [&](int m) {
#pragma unroll
        for (int k = 0; k < 32; k++) {
            if (!(k & m)) {
                int k1 = k | m;
                u64 a = P[k], bb = P[k1];
                P[k]  = fma2(pOne, bb, a);    // a + b
                P[k1] = fma2(mOne, bb, a);    // a - b
            }
        }
    };
    wht_level(16); wht_level(8); wht_level(4); wht_level(2); wht_level(1);
    // Now pack[kappa] = (E_kappa, O_kappa): WHT over even/odd l separately;
    // full frequency mu = (kappa, mu0): value = mu0 ? E-O : E+O.

    float acc[NQ];
    {
        int pit = perm_inv(t << 6);   // runtime per-thread sign factor
#pragma unroll
        for (int q = 0; q < NQ; q++) {
            int mu = 0;               // compile-time: l-restricted perm_inv row
#pragma unroll
            for (int j = 0; j < 6; j++)
                mu |= ((perm_inv(1 << j) >> (11 - q)) & 1) << j;
            float E, O;
            upk2(P[mu >> 1], E, O);
            float s = (mu & 1) ? (E - O) : (E + O);
            acc[q] = __int_as_float(__float_as_int(s) ^
                                    (((pit >> (11 - q)) & 1) << 31));
        }
    }
#pragma unroll
    for (int off = 16; off > 0; off >>= 1) {
#pragma unroll
        for (int q = 0; q < NQ; q++)
            acc[q] += __shfl_xor_sync(0xffffffffu, acc[q], off);
    }
    if ((t & 31) == 0) {
#pragma unroll
        for (int q = 0; q < NQ; q++) atomicAdd(&red[q], acc[q]);
    }
    __syncthreads();
    if (t < NQ) out[b * NQ + t] = red[t] * sS2;  // apply deferred scale once
}

extern "C" void kernel_launch(void* const* d_in, const int* in_sizes, int n_in,
                              void* d_out, int out_size) {
    const float* x = (const float*)d_in[0];   // (64,128,12) float32
    const float* w = (const float*)d_in[1];   // (4,12) float32
    float* out = (float*)d_out;               // (64,128,12) float32
    int B = in_sizes[0] / NQ;                 // 8192
    qsim_kernel<<<B, THREADS>>>(x, w, out);
}

// round 16
// speedup vs baseline: 1.1598x; 1.0121x over previous
#include <cuda_runtime.h>

#define THREADS 64
#define NQ 12
#define DIM 4096

using u64 = unsigned long long;

// ---- packed f32x2 helpers ----
__device__ __forceinline__ u64 pk2(float lo, float hi) {
    u64 r; asm("mov.b64 %0,{%1,%2};" : "=l"(r) : "f"(lo), "f"(hi)); return r;
}
__device__ __forceinline__ void upk2(u64 v, float& lo, float& hi) {
    asm("mov.b64 {%0,%1},%2;" : "=f"(lo), "=f"(hi) : "l"(v));
}
__device__ __forceinline__ u64 fma2(u64 a, u64 b, u64 c) {
    u64 d; asm("fma.rn.f32x2 %0,%1,%2,%3;" : "=l"(d) : "l"(a), "l"(b), "l"(c)); return d;
}
__device__ __forceinline__ u64 mul2(u64 a, u64 b) {
    u64 d; asm("mul.rn.f32x2 %0,%1,%2;" : "=l"(d) : "l"(a), "l"(b)); return d;
}

// Ring-CNOT permutation: new_state[i] = old_state[perm_fwd(i)]
__device__ __forceinline__ int perm_fwd(int i) {
#pragma unroll
    for (int j = 11; j >= 0; j--) {
        int cb = 11 - j;
        int tb = (j == 11) ? 11 : (10 - j);
        i ^= ((i >> cb) & 1) << tb;
    }
    return i;
}
__device__ __forceinline__ int perm_inv(int i) {
#pragma unroll
    for (int j = 0; j < 12; j++) {
        int cb = 11 - j;
        int tb = (j == 11) ? 11 : (10 - j);
        i ^= ((i >> cb) & 1) << tb;
    }
    return i;
}

// Layout A (p1_store scatter -> p2_load private float4):
//   physA(i) = i ^ (((i>>6)&7)<<1)            (unchanged, proven in R11)
// Layout B (p2_store scatter -> p1_load_perm private float4):
//   old amp j stored at AB(perm_inv(j)), with
//   AB(i) = ((i&63)<<6) | (((i>>6)&63) ^ ((i&7)<<1))     (GF(2)-linear)
//   => reader of new-frame amp i=(l<<6)|t finds it at its OWN block
//      (t<<6) | (l ^ ((t&7)<<1)): contiguous float4, banks via k^(t&7).
__device__ __forceinline__ int mapAB(int i) {
    return ((i & 63) << 6) | (((i >> 6) & 63) ^ ((i & 7) << 1));
}

__global__ void __launch_bounds__(THREADS, 6) qsim_kernel(
    const float* __restrict__ x, const float* __restrict__ w,
    float* __restrict__ out)
{
    __shared__ float2 st[DIM];          // 32 KB state
    __shared__ float gc[48], gs[48];    // cos/sin (0-11 = merged encode+layer0)
    __shared__ float gt[48];            // tan(theta/2) (slots 12-47 consumed)
    __shared__ float sLA[16], sLB[16], sLC[16];  // product-state magnitude LUTs
    __shared__ float red[NQ];
    __shared__ float sS2;               // (prod c over gates 12..47)^2

    const int b = blockIdx.x;
    const int t = threadIdx.x;          // 0..63
    const int pt = perm_fwd(t);                 // layer-1 analytic pass
    const int WtB = mapAB(perm_inv(t << 6));    // Layout-B writer thread part

    // Angles: slots 0-11 = x_q + w_{0,q} (RX fusion); 12-47 = w rows 1-3.
    if (t < 48) {
        float th = w[t];
        if (t < NQ) th += x[b * NQ + t];
        float ss, cc;
        sincosf(0.5f * th, &ss, &cc);
        gc[t] = cc; gs[t] = ss;
        gt[t] = ss / cc;
    }
    if (t < NQ) red[t] = 0.0f;
    __syncthreads();

    // Product-state magnitude LUTs over the three 4-bit nibbles (exact c,s).
    if (t < 48) {
        int grp = t >> 4;
        int h = t & 15;
        int qbase = grp * 4;
        float p = 1.0f;
#pragma unroll
        for (int q = 0; q < 4; q++)
            p *= ((h >> (3 - q)) & 1) ? gs[qbase + q] : gc[qbase + q];
        (grp == 0 ? sLA : grp == 1 ? sLB : sLC)[h] = p;
    }
    if (t == 0) {
        float S = 1.0f;
#pragma unroll
        for (int g = 12; g < 48; g++) S *= gc[g];
        sS2 = S * S;
    }

    // SoA packed state: slot k holds LOGICAL amps l=2k, 2k+1 (l = 6 bits).
    u64 X[32], Y[32];

    // pair-bit gate in tangent form on a freshly loaded pair, then pack.
    auto gate_pack = [&](float2 a0, float2 a1, float t1, int k) {
        float nx0 = fmaf( t1, a1.y, a0.x);
        float ny0 = fmaf(-t1, a1.x, a0.y);
        float nx1 = fmaf( t1, a0.y, a1.x);
        float ny1 = fmaf(-t1, a0.x, a1.y);
        X[k] = pk2(nx0, nx1);
        Y[k] = pk2(ny0, ny1);
    };

    // Packed tangent-form RX on pack-space bit pm (k in [0,32)).
    auto rxp = [&](int g, int pm) {
        float tg = gt[g];
        u64 t2 = pk2(tg, tg), m2 = pk2(-tg, -tg);
#pragma unroll
        for (int k = 0; k < 32; k++) {
            if (!(k & pm)) {
                int k1 = k | pm;
                u64 X0 = X[k], Y0 = Y[k], X1 = X[k1], Y1 = Y[k1];
                X[k]  = fma2(t2, Y1, X0);
                Y[k]  = fma2(m2, X1, Y0);
                X[k1] = fma2(t2, Y0, X1);
                Y[k1] = fma2(m2, X0, Y1);
            }
        }
    };
    // pass1: amps i=(l<<6)|t, register bits = qubits 0..5. Packed: qubits 0..4.
    auto packed5_p1 = [&](int g) {
        rxp(g, 16); rxp(g + 1, 8); rxp(g + 2, 4); rxp(g + 3, 2); rxp(g + 4, 1);
    };
    // pass2: amps i=(t<<6)|l, register bits = qubits 6..11. Packed: qubits 6..10.
    auto packed5_p2 = [&](int g) {
        rxp(g + 6, 16); rxp(g + 7, 8); rxp(g + 8, 4); rxp(g + 9, 2); rxp(g + 10, 1);
    };

    // Analytic product-state amplitude: amp = mag(pi) * (-i)^popc(pi)
    auto prod_amp = [&](int pi) -> float2 {
        float mag = sLA[pi >> 8] * sLB[(pi >> 4) & 15] * sLC[pi & 15];
        int kc = __popc(pi) & 3;
        float sm = __int_as_float(__float_as_int(mag) ^ (((kc + 1) & 2) << 30));
        return (kc & 1) ? make_float2(0.0f, sm) : make_float2(sm, 0.0f);
    };

    const int e3 = t & 7;

    // pass1 perm-load (layers 2,3) from Layout B: the reader's data is in its
    // OWN contiguous block -> 32 private float4 loads, slot k compile-time.
    // v.xy = amp l=2k, v.zw = amp l=2k+1 (bank rotation k^e3 inside block).
    auto p1_load_perm = [&](int g) {
        float t1 = gt[g + 5];
        const float4* st4 = reinterpret_cast<const float4*>(st);
        int base = t << 5;
#pragma unroll
        for (int k = 0; k < 32; k++) {
            float4 v = st4[base | (k ^ e3)];
            gate_pack(make_float2(v.x, v.y), make_float2(v.z, v.w), t1, k);
        }
    };
    // pass1 store into Layout A (scatter across threads, conflict-free)
    auto p1_store = [&]() {
#pragma unroll
        for (int k = 0; k < 32; k++) {
            float x0, x1, y0, y1;
            upk2(X[k], x0, x1);
            upk2(Y[k], y0, y1);
            int l0 = 2 * k, l1 = 2 * k + 1;
            st[((l0 << 6) | t) ^ ((l0 & 7) << 1)] = make_float2(x0, y0);
            st[((l1 << 6) | t) ^ ((l1 & 7) << 1)] = make_float2(x1, y1);
        }
    };
    // pass2 float4 load from Layout A (private block); gate = qubit 11 (g+11).
    auto p2_load = [&](int g) {
        float t1 = gt[g + 11];
        const float4* st4 = reinterpret_cast<const float4*>(st);
        int base = t << 5;
#pragma unroll
        for (int k = 0; k < 32; k++) {
            float4 v = st4[base | (k ^ e3)];
            gate_pack(make_float2(v.x, v.y), make_float2(v.z, v.w), t1, k);
        }
    };
    // pass2 store into Layout B: scatter addr = WtB ^ AB(perm_inv(l)),
    // AB-linearity makes the l part compile-time -> one LOP3 per store.
    // Bank field of WtB over t3..t0 is injective (GF(2) rows 1111/1011/1001/1000).
    auto p2_store = [&]() {
#pragma unroll
        for (int k = 0; k < 32; k++) {
            float x0, x1, y0, y1;
            upk2(X[k], x0, x1);
            upk2(Y[k], y0, y1);
            const int C0 = mapAB(perm_inv(2 * k));       // compile-time
            const int C1 = mapAB(perm_inv(2 * k + 1));   // compile-time
            st[WtB ^ C0] = make_float2(x0, y0);
            st[WtB ^ C1] = make_float2(x1, y1);
        }
    };

    __syncthreads();  // LUTs + sS2 ready

    // ---- Layer 1 (gates 12-23): pass1 analytic at perm-permuted indices ----
    {
        float t1 = gt[12 + 5];
#pragma unroll
        for (int k = 0; k < 32; k++)
            gate_pack(prod_amp(perm_fwd((2 * k) << 6) ^ pt),
                      prod_amp(perm_fwd((2 * k + 1) << 6) ^ pt), t1, k);
        packed5_p1(12);
        p1_store(); __syncthreads();
        p2_load(12); packed5_p2(12);
        __syncthreads();               // all private reads done before scatter
        p2_store(); __syncthreads();
    }

    // ---- Layers 2,3 (gates 24-35, 36-47) ----
#pragma unroll 1
    for (int layer = 2; layer <= 3; layer++) {
        int g = layer * 12;
        p1_load_perm(g);
        packed5_p1(g);
        __syncthreads();               // private reads done before scatter
        p1_store(); __syncthreads();
        p2_load(g); packed5_p2(g);
        if (layer < 3) {
            __syncthreads();           // private reads done before scatter
            p2_store(); __syncthreads();
        }
        // layer 3: stays in registers; final perm folded into readout
    }

    // ---- Readout via Walsh-Hadamard transform ----
    u64 P[32];
#pragma unroll
    for (int k = 0; k < 32; k++)
        P[k] = fma2(X[k], X[k], mul2(Y[k], Y[k]));   // packed |amp|^2 pairs

    const u64 pOne = pk2(1.0f, 1.0f), mOne = pk2(-1.0f, -1.0f);
    auto wht_level = [&](int m) {
#pragma unroll
        for (int k = 0; k < 32; k++) {
            if (!(k & m)) {
                int k1 = k | m;
                u64 a = P[k], bb = P[k1];
                P[k]  = fma2(pOne, bb, a);    // a + b
                P[k1] = fma2(mOne, bb, a);    // a - b
            }
        }
    };
    wht_level(16); wht_level(8); wht_level(4); wht_level(2); wht_level(1);

    float acc[NQ];
    {
        int pit = perm_inv(t << 6);   // runtime per-thread sign factor
#pragma unroll
        for (int q = 0; q < NQ; q++) {
            int mu = 0;               // compile-time: l-restricted perm_inv row
#pragma unroll
            for (int j = 0; j < 6; j++)
                mu |= ((perm_inv(1 << j) >> (11 - q)) & 1) << j;
            float E, O;
            upk2(P[mu >> 1], E, O);
            float s = (mu & 1) ? (E - O) : (E + O);
            acc[q] = __int_as_float(__float_as_int(s) ^
                                    (((pit >> (11 - q)) & 1) << 31));
        }
    }
#pragma unroll
    for (int off = 16; off > 0; off >>= 1) {
#pragma unroll
        for (int q = 0; q < NQ; q++)
            acc[q] += __shfl_xor_sync(0xffffffffu, acc[q], off);
    }
    if ((t & 31) == 0) {
#pragma unroll
        for (int q = 0; q < NQ; q++) atomicAdd(&red[q], acc[q]);
    }
    __syncthreads();
    if (t < NQ) out[b * NQ + t] = red[t] * sS2;  // apply deferred scale once
}

extern "C" void kernel_launch(void* const* d_in, const int* in_sizes, int n_in,
                              void* d_out, int out_size) {
    const float* x = (const float*)d_in[0];   // (64,128,12) float32
    const float* w = (const float*)d_in[1];   // (4,12) float32
    float* out = (float*)d_out;               // (64,128,12) float32
    int B = in_sizes[0] / NQ;                 // 8192
    qsim_kernel<<<B, THREADS>>>(x, w, out);
}